// round 11
// baseline (speedup 1.0000x reference)
#include <cuda_runtime.h>

#define PH   8
#define NN   8
#define KK   64
#define CC   128
#define HH   128
#define WW   128
#define HW   (HH * WW)

#define CPB       8      // channels per valid-kernel block
#define TPB_V     512
#define TPB_P     256
#define PLANES_PB 16     // (d,c) planes per pad-kernel block (256 planes / 16 blocks)

// Box decode shared by both kernels.
__device__ __forceinline__ int box_width(const float4 b,
                                         float& xmin, float& ymin,
                                         float& bwf, float& bhf, bool& wide)
{
    xmin = b.x; ymin = b.y;
    const float xmax = b.z, ymax = b.w;
    const bool valid_box = !(xmin == 0.f && ymin == 0.f && xmax == 0.f && ymax == 0.f);
    bwf = valid_box ? (xmax - xmin) : 1.f;
    bhf = valid_box ? (ymax - ymin) : 1.f;
    wide = bwf > bhf;
    const float ratio = wide ? (bwf / bhf) : (bhf / bwf);
    return valid_box ? (int)ceilf(ratio * (float)PH) : 0;
}

// ---------------------------------------------------------------------------
// Kernel 1: padding fill. For box nk, zero columns j in [width, MW) of all
// PLANES_PB (d,c) planes this block owns. Pure uniform stores, no gathers.
// ---------------------------------------------------------------------------
__global__ void __launch_bounds__(TPB_P)
bbp_pad_kernel(const float* __restrict__ boxes,
               float* __restrict__ feats,
               float* __restrict__ widths,
               int MW)
{
    const int nk  = blockIdx.x;
    const int by  = blockIdx.y;
    const int tid = threadIdx.x;

    float xmin, ymin, bwf, bhf; bool wide;
    const int width = box_width(reinterpret_cast<const float4*>(boxes)[nk],
                                xmin, ymin, bwf, bhf, wide);

    if (tid == 0 && by == 0) {
        widths[(size_t)nk * 2 + 0] = (float)width;
        widths[(size_t)nk * 2 + 1] = (float)width;
    }

    const int nij = PH * MW;
    const int P   = MW - width;
    if (P <= 0) return;

    const int total = PH * P;
    const unsigned magic_p =
        (unsigned)((0x100000000ULL + (unsigned)P - 1) / (unsigned)P);

    #pragma unroll
    for (int pl = 0; pl < PLANES_PB; ++pl) {
        const int p = by * PLANES_PB + pl;      // plane id in [0, 256)
        const int d = p >> 7;
        const int c = p & (CC - 1);
        float* __restrict__ base =
            feats + (((size_t)nk * 2 + d) * CC + c) * nij + width;
        for (int t = tid; t < total; t += TPB_P) {
            const int row = (int)__umulhi((unsigned)t, magic_p);
            const int jj  = t - row * P;
            __stwt(base + row * MW + jj, 0.f);
        }
    }
}

// ---------------------------------------------------------------------------
// Kernel 2: dense valid positions. tid in [0, nv = PH*width); every lane is a
// real gather. Record computed once; 32 independent LDGs batched, then 16
// coalesced stores (forward plane + exact-flip plane).
// ---------------------------------------------------------------------------
__global__ void __launch_bounds__(TPB_V)
bbp_valid_kernel(const float* __restrict__ x,
                 const float* __restrict__ boxes,
                 float* __restrict__ feats,
                 int MW)
{
    const int nk  = blockIdx.x;            // n*KK + k
    const int n   = nk >> 6;
    const int cc0 = blockIdx.y * CPB;
    const int tid = threadIdx.x;

    float xmin, ymin, bwf, bhf; bool wide;
    const int width = box_width(reinterpret_cast<const float4*>(boxes)[nk],
                                xmin, ymin, bwf, bhf, wide);

    const int nv = PH * width;
    if (tid >= nv) return;

    const float wf      = (float)(width > 2 ? width : 2);
    const float inv_wf1 = 1.0f / (wf - 1.0f);
    const float inv_ph1 = 1.0f / (float)(PH - 1);
    const int   nij     = PH * MW;

    // dense decode: (i,j) = divmod(tid, width)
    const unsigned magic_w =
        (unsigned)((0x100000000ULL + (unsigned)width - 1) / (unsigned)width);
    const int i = (int)__umulhi((unsigned)tid, magic_w);
    const int j = tid - i * width;

    const int e0 = i * MW + j;                             // d=0 destination
    const int d1 = (PH - 1 - i) * MW + (width - 1 - j);    // d=1 destination

    float px, py;
    const float fi = (float)i, fj = (float)j;
    if (wide) {
        px = xmin + fj * bwf * inv_wf1;
        py = ymin + fi * bhf * inv_ph1;
    } else {
        px = xmin + fi * bwf * inv_ph1;
        py = ymin + (wf - fj) * bhf * inv_wf1;
    }
    const float ix = px - 0.5f;       // grid normalize/unnormalize cancels exactly
    const float iy = py - 0.5f;
    const float x0f = floorf(ix), y0f = floorf(iy);
    const int x0 = (int)x0f, y0 = (int)y0f;
    const int x1 = x0 + 1,   y1 = y0 + 1;
    const float dx = ix - x0f, dy = iy - y0f;
    const float wx0 = 1.f - dx, wx1 = dx;
    const float wy0 = 1.f - dy, wy1 = dy;
    const bool vx0 = (x0 >= 0) & (x0 < WW);
    const bool vx1 = (x1 >= 0) & (x1 < WW);
    const bool vy0 = (y0 >= 0) & (y0 < HH);
    const bool vy1 = (y1 >= 0) & (y1 < HH);
    const float w00 = (vx0 & vy0) ? wx0 * wy0 : 0.f;
    const float w10 = (vx1 & vy0) ? wx1 * wy0 : 0.f;
    const float w01 = (vx0 & vy1) ? wx0 * wy1 : 0.f;
    const float w11 = (vx1 & vy1) ? wx1 * wy1 : 0.f;
    const int xc0 = min(max(x0, 0), WW - 1);
    const int xc1 = min(max(x1, 0), WW - 1);
    const int yc0 = min(max(y0, 0), HH - 1);
    const int yc1 = min(max(y1, 0), HH - 1);
    const int o00 = yc0 * WW + xc0;
    const int o10 = yc0 * WW + xc1;
    const int o01 = yc1 * WW + xc0;
    const int o11 = yc1 * WW + xc1;

    // gather phase: all channels first (32 independent LDGs in flight)
    const float* __restrict__ xbase = x + ((size_t)n * CC + cc0) * HW;
    float v[CPB];
    #pragma unroll
    for (int c = 0; c < CPB; ++c) {
        const float* __restrict__ xc = xbase + (size_t)c * HW;
        v[c] = w00 * __ldg(xc + o00)
             + w10 * __ldg(xc + o10)
             + w01 * __ldg(xc + o01)
             + w11 * __ldg(xc + o11);
    }

    // store phase: both planes coalesced (forward / reverse-contiguous)
    float* __restrict__ out0 = feats + (((size_t)nk * 2 + 0) * CC + cc0) * nij + e0;
    float* __restrict__ out1 = feats + (((size_t)nk * 2 + 1) * CC + cc0) * nij + d1;
    #pragma unroll
    for (int c = 0; c < CPB; ++c) {
        __stwt(out0 + (size_t)c * nij, v[c]);
        __stwt(out1 + (size_t)c * nij, v[c]);
    }
}

extern "C" void kernel_launch(void* const* d_in, const int* in_sizes, int n_in,
                              void* d_out, int out_size)
{
    const float* x     = (const float*)d_in[0];
    const float* boxes = (const float*)d_in[1];
    float* out = (float*)d_out;

    // out = concat(feats (N,K,2,C,PH,MW), widths (N,K,2))
    const long long widths_elems = (long long)NN * KK * 2;               // 1024
    const long long per_mw       = (long long)NN * KK * 2 * CC * PH;     // 1048576
    int MW = (int)(((long long)out_size - widths_elems) / per_mw);
    if (MW < 1) MW = 1;
    if (MW > 64) MW = 64;   // width <= 64 by construction (ratio < 8)

    float* feats  = out;
    float* widths = out + (size_t)per_mw * MW;

    // Disjoint regions: order of the two kernels is irrelevant.
    dim3 grid_p(NN * KK, (2 * CC) / PLANES_PB);   // (512, 16)
    bbp_pad_kernel<<<grid_p, TPB_P>>>(boxes, feats, widths, MW);

    dim3 grid_v(NN * KK, CC / CPB);               // (512, 16)
    bbp_valid_kernel<<<grid_v, TPB_V>>>(x, boxes, feats, MW);
}

// round 12
// speedup vs baseline: 2.1987x; 2.1987x over previous
#include <cuda_runtime.h>

#define PH   8
#define NN   8
#define KK   64
#define CC   128
#define HH   128
#define WW   128
#define HW   (HH * WW)

#define CPB   8                  // channels per block
#define TPB   256                // one pair (2 positions) per thread; pairs <= 256

// One block: one (n,k) box, BOTH directions d=0/1, CPB channels.
// Key identity: the d=1 plane is a PURE LINEAR MIRROR of the d=0 plane:
//   plane1[phi(e)] = plane0_value(e),  phi(e) = (e <= C1) ? C1 - e : e,
//   C1 = (PH-1)*MW + width - 1  (block-uniform).
// phi is a bijection mapping valid->flipped-valid and padding->padding, so
// pair stores to plane1 are contiguous-reversed with alignment decided ONCE
// per block by parity of C1 -> vector stores with no warp divergence.

__global__ void __launch_bounds__(TPB)
bbp_kernel(const float* __restrict__ x,
           const float* __restrict__ boxes,
           float* __restrict__ feats,
           float* __restrict__ widths,
           int MW)
{
    const int nk  = blockIdx.x;            // n*KK + k
    const int n   = nk >> 6;
    const int cc0 = blockIdx.y * CPB;
    const int tid = threadIdx.x;

    // ---- box parameters (uniform per block) ----
    const float4 b = reinterpret_cast<const float4*>(boxes)[nk];
    const float xmin = b.x, ymin = b.y, xmax = b.z, ymax = b.w;
    const bool valid_box = !(xmin == 0.f && ymin == 0.f && xmax == 0.f && ymax == 0.f);
    const float bwf = valid_box ? (xmax - xmin) : 1.f;
    const float bhf = valid_box ? (ymax - ymin) : 1.f;
    const bool wide = bwf > bhf;
    const float ratio = wide ? (bwf / bhf) : (bhf / bwf);
    const int   width = valid_box ? (int)ceilf(ratio * (float)PH) : 0;
    const float wf    = (float)(width > 2 ? width : 2);
    const float inv_wf1 = 1.0f / (wf - 1.0f);
    const float inv_ph1 = 1.0f / (float)(PH - 1);

    const int nij   = PH * MW;             // multiple of 8
    const int pairs = nij >> 1;            // <= 256

    if (tid == 0 && blockIdx.y == 0) {
        widths[(size_t)nk * 2 + 0] = (float)width;
        widths[(size_t)nk * 2 + 1] = (float)width;
    }
    if (tid >= pairs) return;

    const int p  = tid << 1;                          // pair start (even)
    const int C1 = (PH - 1) * MW + width - 1;         // mirror constant

    // exact floor(pos/MW) for pos < 512 via magic multiply
    const unsigned magic = (unsigned)((0x100000000ULL + (unsigned)MW - 1) / (unsigned)MW);

    // ---- per-thread records for the 2 positions (computed once) ----
    unsigned off_a[2];   // packed: off00 | off10<<16
    unsigned off_b[2];   // packed: off01 | off11<<16
    float4   wt[2];
    unsigned vmask = 0;

    #pragma unroll
    for (int s = 0; s < 2; ++s) {
        const int pos = p + s;
        const int i = (int)__umulhi((unsigned)pos, magic);
        const int j = pos - i * MW;
        off_a[s] = 0; off_b[s] = 0;
        wt[s] = make_float4(0.f, 0.f, 0.f, 0.f);
        if (j < width) {
            vmask |= (1u << s);
            float px, py;
            const float fi = (float)i, fj = (float)j;
            if (wide) {
                px = xmin + fj * bwf * inv_wf1;
                py = ymin + fi * bhf * inv_ph1;
            } else {
                px = xmin + fi * bwf * inv_ph1;
                py = ymin + (wf - fj) * bhf * inv_wf1;
            }
            const float ix = px - 0.5f;   // grid normalize/unnormalize cancels
            const float iy = py - 0.5f;
            const float x0f = floorf(ix), y0f = floorf(iy);
            const int x0 = (int)x0f, y0 = (int)y0f;
            const int x1 = x0 + 1,   y1 = y0 + 1;
            const float dx = ix - x0f, dy = iy - y0f;
            const float wx0 = 1.f - dx, wx1 = dx;
            const float wy0 = 1.f - dy, wy1 = dy;
            const bool vx0 = (x0 >= 0) & (x0 < WW);
            const bool vx1 = (x1 >= 0) & (x1 < WW);
            const bool vy0 = (y0 >= 0) & (y0 < HH);
            const bool vy1 = (y1 >= 0) & (y1 < HH);
            wt[s].x = (vx0 & vy0) ? wx0 * wy0 : 0.f;
            wt[s].y = (vx1 & vy0) ? wx1 * wy0 : 0.f;
            wt[s].z = (vx0 & vy1) ? wx0 * wy1 : 0.f;
            wt[s].w = (vx1 & vy1) ? wx1 * wy1 : 0.f;
            const unsigned xc0 = (unsigned)min(max(x0, 0), WW - 1);
            const unsigned xc1 = (unsigned)min(max(x1, 0), WW - 1);
            const unsigned yc0 = (unsigned)min(max(y0, 0), HH - 1);
            const unsigned yc1 = (unsigned)min(max(y1, 0), HH - 1);
            off_a[s] = (yc0 * WW + xc0) | ((yc0 * WW + xc1) << 16);
            off_b[s] = (yc1 * WW + xc0) | ((yc1 * WW + xc1) << 16);
        }
    }

    // out1 addressing modes (region-uniform within the block)
    const bool tail = (p > C1);            // whole pair in padding tail (v==0)
    const bool mir  = (p + 1 <= C1);       // whole pair mirrored
    const bool oddC = ((C1 & 1) != 0);     // mirrored pairs 8B-aligned (block-uniform)

    const float* __restrict__ xbase = x + ((size_t)n * CC + cc0) * HW;
    float* __restrict__ f0 = feats + (((size_t)nk * 2 + 0) * CC + cc0) * nij;
    float* __restrict__ f1 = feats + (((size_t)nk * 2 + 1) * CC + cc0) * nij;

    // ---- channel groups of 4: 32 independent LDGs in flight per group ----
    #pragma unroll
    for (int g = 0; g < CPB; g += 4) {
        float v0[4], v1[4];
        #pragma unroll
        for (int c = 0; c < 4; ++c) {
            const float* __restrict__ xc = xbase + (size_t)(g + c) * HW;
            v0[c] = 0.f; v1[c] = 0.f;
            if (vmask & 1u) {
                v0[c] = wt[0].x * __ldg(xc + (off_a[0] & 0xFFFFu))
                      + wt[0].y * __ldg(xc + (off_a[0] >> 16))
                      + wt[0].z * __ldg(xc + (off_b[0] & 0xFFFFu))
                      + wt[0].w * __ldg(xc + (off_b[0] >> 16));
            }
            if (vmask & 2u) {
                v1[c] = wt[1].x * __ldg(xc + (off_a[1] & 0xFFFFu))
                      + wt[1].y * __ldg(xc + (off_a[1] >> 16))
                      + wt[1].z * __ldg(xc + (off_b[1] & 0xFFFFu))
                      + wt[1].w * __ldg(xc + (off_b[1] >> 16));
            }
        }

        #pragma unroll
        for (int c = 0; c < 4; ++c) {
            float* __restrict__ o0 = f0 + (size_t)(g + c) * nij;
            float* __restrict__ o1 = f1 + (size_t)(g + c) * nij;

            // d=0 plane: forward vector store (p even, plane base 32B-aligned)
            __stwt(reinterpret_cast<float2*>(o0 + p), make_float2(v0[c], v1[c]));

            // d=1 plane via mirror phi
            if (tail) {
                // both positions self-mapped padding: forward vector zero
                __stwt(reinterpret_cast<float2*>(o1 + p), make_float2(0.f, 0.f));
            } else if (mir & oddC) {
                // contiguous reversed, aligned (C1 odd, block-uniform)
                __stwt(reinterpret_cast<float2*>(o1 + (C1 - p - 1)),
                       make_float2(v1[c], v0[c]));
            } else {
                // mirrored but misaligned, or the single straddle pair (p == C1)
                const int a0 = (p     <= C1) ? (C1 - p)     : p;
                const int a1 = (p + 1 <= C1) ? (C1 - p - 1) : (p + 1);
                __stwt(o1 + a0, v0[c]);
                __stwt(o1 + a1, v1[c]);
            }
        }
    }
}

extern "C" void kernel_launch(void* const* d_in, const int* in_sizes, int n_in,
                              void* d_out, int out_size)
{
    const float* x     = (const float*)d_in[0];
    const float* boxes = (const float*)d_in[1];
    float* out = (float*)d_out;

    // out = concat(feats (N,K,2,C,PH,MW), widths (N,K,2))
    const long long widths_elems = (long long)NN * KK * 2;               // 1024
    const long long per_mw       = (long long)NN * KK * 2 * CC * PH;     // 1048576
    int MW = (int)(((long long)out_size - widths_elems) / per_mw);
    if (MW < 1) MW = 1;
    if (MW > 64) MW = 64;   // nij <= 512 by construction (ratio < 8)

    float* feats  = out;
    float* widths = out + (size_t)per_mw * MW;

    dim3 grid(NN * KK, CC / CPB);
    bbp_kernel<<<grid, TPB>>>(x, boxes, feats, widths, MW);
}